// round 1
// baseline (speedup 1.0000x reference)
#include <cuda_runtime.h>
#include <cuda_bf16.h>

// Problem constants (fixed shapes for this problem)
#define H     200      // history length
#define D     128      // embed/hidden size
#define NT    256      // threads per CTA
#define WKS   132      // padded row stride for WkT (16B aligned, fewer STS conflicts)

// smem layout (bytes):
//  As   [D][H]  fp32 : 128*200*4 = 102400   (A transposed: As[e][r] = hist_emb[r][e])
//  WkT  [D][WKS] fp32: 128*132*4 =  67584   (WkT[e][c] = Wk[c][e])
//  kb   [H*D]  bf16  : 25600*2   =  51200   (k flat, j = r*128+c)
//  tgt_s[128] q_s[128] tv_s[128] fp32 : 1536
//  hidx_s[200] hreg_s[200] int          : 1600
//  red[32] fp32                          : 128
#define OFF_AS    0
#define OFF_WKT   102400
#define OFF_KB    169984
#define OFF_TGT   221184
#define OFF_Q     221696
#define OFF_TV    222208
#define OFF_HIDX  222720
#define OFF_HREG  223520
#define OFF_RED   224320
#define SMEM_BYTES 224448

__device__ float g_geo[1024];   // per-i geo coefficient  g[i] = -1/(relu(s_i)+1)

// ---------------------------------------------------------------------------
// Kernel 1: cross-batch geo reduction.  s[j] = sum_b erow[tr[b]] * erow[hr[b,j]]
// ---------------------------------------------------------------------------
__global__ void geo_kernel(const int* __restrict__ hr, const int* __restrict__ tr,
                           const float* __restrict__ embD, const int* __restrict__ uidp,
                           int b, int region_num) {
    __shared__ float red[8];
    const float* erow = embD + (size_t)uidp[0] * (size_t)region_num;
    int j = blockIdx.x;
    float s = 0.f;
    for (int bb = threadIdx.x; bb < b; bb += blockDim.x)
        s += erow[tr[bb]] * erow[hr[bb * H + j]];
    int lane = threadIdx.x & 31, w = threadIdx.x >> 5;
#pragma unroll
    for (int o = 16; o; o >>= 1) s += __shfl_down_sync(0xffffffffu, s, o);
    if (lane == 0) red[w] = s;
    __syncthreads();
    if (threadIdx.x == 0) {
        float t = 0.f;
#pragma unroll
        for (int i = 0; i < 8; i++) t += red[i];
        float r = fmaxf(t, 0.f);
        g_geo[j] = -1.0f / (r + 1.0f);
    }
}

// ---------------------------------------------------------------------------
// Block-wide sum over 256 threads
// ---------------------------------------------------------------------------
__device__ __forceinline__ float block_sum(float v, float* red) {
    int lane = threadIdx.x & 31, w = threadIdx.x >> 5;
#pragma unroll
    for (int o = 16; o; o >>= 1) v += __shfl_down_sync(0xffffffffu, v, o);
    __syncthreads();                 // protect red from previous use
    if (lane == 0) red[w] = v;
    __syncthreads();
    float s = (threadIdx.x < 8) ? red[threadIdx.x] : 0.f;
    if (w == 0) {
#pragma unroll
        for (int o = 4; o; o >>= 1) s += __shfl_down_sync(0xffffffffu, s, o);
        if (lane == 0) red[0] = s;
    }
    __syncthreads();
    return red[0];
}

// ---------------------------------------------------------------------------
// Kernel 2: one CTA per batch element. Fused gather + K GEMM + scores +
// attention + geo + final bilinear reduction.
// ---------------------------------------------------------------------------
__global__ __launch_bounds__(NT, 1)
void main_kernel(const int* __restrict__ history, const int* __restrict__ target,
                 const int* __restrict__ hregion, const int* __restrict__ tregion,
                 const float* __restrict__ hv, const float* __restrict__ dist,
                 const float* __restrict__ embT, const float* __restrict__ embR,
                 const float* __restrict__ Wq, const float* __restrict__ Wk,
                 const float* __restrict__ Wv, float* __restrict__ out) {
    extern __shared__ char smem[];
    float*          As     = (float*)(smem + OFF_AS);     // [D][H]
    float*          WkT    = (float*)(smem + OFF_WKT);    // [D][WKS]
    __nv_bfloat16*  kb     = (__nv_bfloat16*)(smem + OFF_KB);
    float*          tgt_s  = (float*)(smem + OFF_TGT);
    float*          q_s    = (float*)(smem + OFF_Q);
    float*          tv_s   = (float*)(smem + OFF_TV);
    int*            hidx_s = (int*)(smem + OFF_HIDX);
    int*            hreg_s = (int*)(smem + OFF_HREG);
    float*          red    = (float*)(smem + OFF_RED);

    const int b   = blockIdx.x;
    const int tid = threadIdx.x;
    const int tgt_i  = target[b];
    const int treg_i = tregion[b];

    // ---- phase 0: indices + target embedding -----------------------------
    for (int r = tid; r < H; r += NT) {
        hidx_s[r] = history[b * H + r];
        hreg_s[r] = hregion[b * H + r];
    }
    if (tid < D) {
        int e = tid;
        tgt_s[e] = (e < 64) ? embT[(size_t)tgt_i * 64 + e]
                            : embR[(size_t)treg_i * 64 + (e - 64)];
    }
    __syncthreads();

    // ---- phase 1: gather history embeddings (transposed) + WkT + q/tv ----
    for (int idx = tid; idx < H * D; idx += NT) {
        int r = idx >> 7, e = idx & 127;
        float v = (e < 64) ? embT[(size_t)hidx_s[r] * 64 + e]
                           : embR[(size_t)hreg_s[r] * 64 + (e - 64)];
        As[e * H + r] = v;
    }
    for (int idx = tid; idx < D * D; idx += NT) {
        int c = idx >> 7, e = idx & 127;
        WkT[e * WKS + c] = Wk[idx];
    }
    if (tid < 128) {                       // q[c] = sum_e tgt[e]*Wq[c,e]
        int c = tid; float acc = 0.f;
#pragma unroll 8
        for (int e = 0; e < D; e++) acc += tgt_s[e] * Wq[c * D + e];
        q_s[c] = acc;
    } else {                               // tv[e] = sum_c tgt[c]*Wv[c,e]
        int e = tid - 128; float acc = 0.f;
#pragma unroll 8
        for (int c = 0; c < D; c++) acc += tgt_s[c] * Wv[c * D + e];
        tv_s[e] = acc;
    }
    __syncthreads();

    // ---- phase 2: K GEMM, 4x4 register tiles, output bf16 to kb ----------
    // k[r][c] = sum_e As[e][r] * WkT[e][c]
    for (int tile = tid; tile < (H / 4) * 32; tile += NT) {
        int rt = tile >> 5, ct = tile & 31;
        const float* Ap = As  + (rt << 2);
        const float* Wp = WkT + (ct << 2);
        float4 a0 = {0,0,0,0}, a1 = {0,0,0,0}, a2 = {0,0,0,0}, a3 = {0,0,0,0};
#pragma unroll 8
        for (int e = 0; e < D; e++) {
            const float4 a = *reinterpret_cast<const float4*>(Ap + e * H);
            const float4 w = *reinterpret_cast<const float4*>(Wp + e * WKS);
            a0.x += a.x * w.x; a0.y += a.x * w.y; a0.z += a.x * w.z; a0.w += a.x * w.w;
            a1.x += a.y * w.x; a1.y += a.y * w.y; a1.z += a.y * w.z; a1.w += a.y * w.w;
            a2.x += a.z * w.x; a2.y += a.z * w.y; a2.z += a.z * w.z; a2.w += a.z * w.w;
            a3.x += a.w * w.x; a3.y += a.w * w.y; a3.z += a.w * w.z; a3.w += a.w * w.w;
        }
        int r0 = rt << 2, c0 = ct << 2;
        __nv_bfloat16* p;
        p = kb + (r0 + 0) * D + c0;
        *(__nv_bfloat162*)(p)     = __floats2bfloat162_rn(a0.x, a0.y);
        *(__nv_bfloat162*)(p + 2) = __floats2bfloat162_rn(a0.z, a0.w);
        p = kb + (r0 + 1) * D + c0;
        *(__nv_bfloat162*)(p)     = __floats2bfloat162_rn(a1.x, a1.y);
        *(__nv_bfloat162*)(p + 2) = __floats2bfloat162_rn(a1.z, a1.w);
        p = kb + (r0 + 2) * D + c0;
        *(__nv_bfloat162*)(p)     = __floats2bfloat162_rn(a2.x, a2.y);
        *(__nv_bfloat162*)(p + 2) = __floats2bfloat162_rn(a2.z, a2.w);
        p = kb + (r0 + 3) * D + c0;
        *(__nv_bfloat162*)(p)     = __floats2bfloat162_rn(a3.x, a3.y);
        *(__nv_bfloat162*)(p + 2) = __floats2bfloat162_rn(a3.z, a3.w);
    }
    __syncthreads();

    // ---- phase 3: scores via the faithful reshape, masked exp ------------
    // scores[i] = sum_x q[x] * kflat[200*x + i]   (kflat = kb, j = r*128+c)
    float me = 0.f;
    if (tid < H) {
        float sc = 0.f;
#pragma unroll 8
        for (int x = 0; x < D; x++)
            sc += q_s[x] * __bfloat162float(kb[x * H + tid]);
        sc *= 0.088388347648318447f;               // 1/sqrt(128)
        me = (hidx_s[tid] != tgt_i) ? expf(sc) : 0.f;
    }
    float S = block_sum(me, red);

    // ---- phase 4: attn + geo weights, final bilinear reduction -----------
    float contrib = 0.f;
    if (tid < H) {
        float attn = me / sqrtf(S);                           // exp_sum ** 0.5
        float geo  = expf(g_geo[tid] * dist[b * H + tid]);
        float w    = attn + geo;
        float dv = 0.f, dt = 0.f;
#pragma unroll 8
        for (int e = 0; e < D; e++) {
            float a = As[e * H + tid];
            dv += a * tv_s[e];                                // hist_i . (tgt@Wv)
            dt += a * tgt_s[e];                               // hist_i . tgt
        }
        contrib = w * dv + hv[tid] * dt;
    }
    float pred = block_sum(contrib, red);
    if (tid == 0) out[b] = 1.0f / (1.0f + expf(-pred));
}

// ---------------------------------------------------------------------------
extern "C" void kernel_launch(void* const* d_in, const int* in_sizes, int n_in,
                              void* d_out, int out_size) {
    const int*   history = (const int*)  d_in[0];
    const int*   target  = (const int*)  d_in[1];
    const int*   hregion = (const int*)  d_in[2];
    const int*   tregion = (const int*)  d_in[3];
    const float* hv      = (const float*)d_in[4];
    const float* dist    = (const float*)d_in[5];
    const int*   uid     = (const int*)  d_in[6];
    const float* embT    = (const float*)d_in[7];
    const float* embR    = (const float*)d_in[8];
    const float* embD    = (const float*)d_in[9];
    const float* Wq      = (const float*)d_in[10];
    const float* Wk      = (const float*)d_in[11];
    const float* Wv      = (const float*)d_in[12];
    float*       out     = (float*)d_out;

    int b          = in_sizes[1];          // 1024
    int region_num = in_sizes[8] / 64;     // 1000

    cudaFuncSetAttribute(main_kernel, cudaFuncAttributeMaxDynamicSharedMemorySize,
                         SMEM_BYTES);

    geo_kernel<<<H, NT>>>(hregion, tregion, embD, uid, b, region_num);
    main_kernel<<<b, NT, SMEM_BYTES>>>(history, target, hregion, tregion,
                                       hv, dist, embT, embR, Wq, Wk, Wv, out);
}

// round 2
// speedup vs baseline: 2.6184x; 2.6184x over previous
#include <cuda_runtime.h>
#include <cuda_bf16.h>
#include <cstdint>

// Problem constants (fixed shapes)
#define H     200
#define D     128
#define NT    256
#define ASD   136     // As row stride in bf16 elems (+8 pad: conflict-free ldmatrix)
#define WKD   136     // Wkb row stride
#define KBD   136     // kb row stride (padded; phase3 translates flat index)
#define MROWS 208     // H padded to 13 m-tiles of 16

// smem layout (bytes, all 16B-aligned)
#define OFF_AS   0
#define SZ_AS    (MROWS*ASD*2)            // 56576
#define OFF_WK   (OFF_AS + SZ_AS)
#define SZ_WK    (128*WKD*2)              // 34816
#define OFF_KB   (OFF_WK + SZ_WK)
#define SZ_KB    (MROWS*KBD*2)            // 56576
#define OFF_TGT  (OFF_KB + SZ_KB)
#define OFF_Q    (OFF_TGT + 512)
#define OFF_TV   (OFF_Q + 512)
#define OFF_HIDX (OFF_TV + 512)
#define OFF_HREG (OFF_HIDX + 800)
#define OFF_RED  (OFF_HREG + 800)
#define SMEM_BYTES (OFF_RED + 128)        // 151232

__device__ float g_geo[1024];   // g[i] = -1/(relu(s_i)+1), batch-independent

// ---------------------------------------------------------------------------
// Kernel 1: cross-batch geo reduction.  s[j] = sum_b erow[tr[b]] * erow[hr[b,j]]
// ---------------------------------------------------------------------------
__global__ void geo_kernel(const int* __restrict__ hr, const int* __restrict__ tr,
                           const float* __restrict__ embD, const int* __restrict__ uidp,
                           int b, int region_num) {
    __shared__ float red[8];
    const float* erow = embD + (size_t)uidp[0] * (size_t)region_num;
    int j = blockIdx.x;
    float s = 0.f;
    for (int bb = threadIdx.x; bb < b; bb += blockDim.x)
        s += erow[tr[bb]] * erow[hr[bb * H + j]];
    int lane = threadIdx.x & 31, w = threadIdx.x >> 5;
#pragma unroll
    for (int o = 16; o; o >>= 1) s += __shfl_down_sync(0xffffffffu, s, o);
    if (lane == 0) red[w] = s;
    __syncthreads();
    if (threadIdx.x == 0) {
        float t = 0.f;
#pragma unroll
        for (int i = 0; i < 8; i++) t += red[i];
        g_geo[j] = -1.0f / (fmaxf(t, 0.f) + 1.0f);
    }
}

// ---------------------------------------------------------------------------
__device__ __forceinline__ float block_sum(float v, float* red) {
    int lane = threadIdx.x & 31, w = threadIdx.x >> 5;
#pragma unroll
    for (int o = 16; o; o >>= 1) v += __shfl_down_sync(0xffffffffu, v, o);
    __syncthreads();
    if (lane == 0) red[w] = v;
    __syncthreads();
    float s = (threadIdx.x < 8) ? red[threadIdx.x] : 0.f;
    if (w == 0) {
#pragma unroll
        for (int o = 4; o; o >>= 1) s += __shfl_down_sync(0xffffffffu, s, o);
        if (lane == 0) red[0] = s;
    }
    __syncthreads();
    return red[0];
}

__device__ __forceinline__ void ldsm4(unsigned& r0, unsigned& r1, unsigned& r2,
                                      unsigned& r3, uint32_t addr) {
    asm volatile("ldmatrix.sync.aligned.m8n8.x4.shared.b16 {%0,%1,%2,%3}, [%4];\n"
                 : "=r"(r0), "=r"(r1), "=r"(r2), "=r"(r3) : "r"(addr));
}

__device__ __forceinline__ void mma16816(float* c, unsigned a0, unsigned a1,
                                         unsigned a2, unsigned a3,
                                         unsigned b0, unsigned b1) {
    asm volatile("mma.sync.aligned.m16n8k16.row.col.f32.bf16.bf16.f32 "
                 "{%0,%1,%2,%3}, {%4,%5,%6,%7}, {%8,%9}, {%0,%1,%2,%3};\n"
                 : "+f"(c[0]), "+f"(c[1]), "+f"(c[2]), "+f"(c[3])
                 : "r"(a0), "r"(a1), "r"(a2), "r"(a3), "r"(b0), "r"(b1));
}

// ---------------------------------------------------------------------------
// Kernel 2: one CTA per batch element.
// ---------------------------------------------------------------------------
__global__ __launch_bounds__(NT, 1)
void main_kernel(const int* __restrict__ history, const int* __restrict__ target,
                 const int* __restrict__ hregion, const int* __restrict__ tregion,
                 const float* __restrict__ hv, const float* __restrict__ dist,
                 const float* __restrict__ embT, const float* __restrict__ embR,
                 const float* __restrict__ Wq, const float* __restrict__ Wk,
                 const float* __restrict__ Wv, float* __restrict__ out) {
    extern __shared__ char smem[];
    __nv_bfloat16* As   = (__nv_bfloat16*)(smem + OFF_AS);   // [208][136]
    __nv_bfloat16* Wkb  = (__nv_bfloat16*)(smem + OFF_WK);   // [128][136]
    __nv_bfloat16* kb   = (__nv_bfloat16*)(smem + OFF_KB);   // [208][136]
    float* tgt_s  = (float*)(smem + OFF_TGT);
    float* q_s    = (float*)(smem + OFF_Q);
    float* tv_s   = (float*)(smem + OFF_TV);
    int*   hidx_s = (int*)(smem + OFF_HIDX);
    int*   hreg_s = (int*)(smem + OFF_HREG);
    float* red    = (float*)(smem + OFF_RED);

    const int b    = blockIdx.x;
    const int tid  = threadIdx.x;
    const int wid  = tid >> 5, lane = tid & 31;
    const int tgt_i  = target[b];
    const int treg_i = tregion[b];

    // ---- phase 0: indices + target embedding (fp32) ----------------------
    for (int r = tid; r < H; r += NT) {
        hidx_s[r] = history[b * H + r];
        hreg_s[r] = hregion[b * H + r];
    }
    if (tid < D)
        tgt_s[tid] = (tid < 64) ? embT[(size_t)tgt_i * 64 + tid]
                                : embR[(size_t)treg_i * 64 + (tid - 64)];
    __syncthreads();

    // ---- phase 1: stage Wk (bf16), gather A (bf16), compute q & tv -------
    for (int i2 = tid; i2 < 8192; i2 += NT) {               // Wk -> smem bf16
        int c = i2 >> 6, e2 = (i2 & 63) << 1;
        float2 v = *(const float2*)(Wk + c * D + e2);
        *(__nv_bfloat162*)&Wkb[c * WKD + e2] = __floats2bfloat162_rn(v.x, v.y);
    }
    for (int i2 = tid; i2 < 12800; i2 += NT) {              // gather hist_emb
        int r = i2 >> 6, ep = (i2 & 63) << 1;
        const float* src = (ep < 64) ? (embT + (size_t)hidx_s[r] * 64 + ep)
                                     : (embR + (size_t)hreg_s[r] * 64 + (ep - 64));
        float2 v = *(const float2*)src;
        *(__nv_bfloat162*)&As[r * ASD + ep] = __floats2bfloat162_rn(v.x, v.y);
    }
    for (int i = tid; i < 512; i += NT) {                   // zero pad rows
        int r = 200 + (i >> 6), ep = (i & 63) << 1;
        *(__nv_bfloat162*)&As[r * ASD + ep] = __floats2bfloat162_rn(0.f, 0.f);
    }
    if (wid < 4) {
        // q[c] = sum_e tgt[e]*Wq[c,e]; warp handles 32 c, batches of 8 for MLP
        float4 tg = *(const float4*)&tgt_s[lane * 4];
        for (int cb = 0; cb < 32; cb += 8) {
            float p[8];
#pragma unroll
            for (int j = 0; j < 8; j++) {
                int c = wid * 32 + cb + j;
                float4 wv = *(const float4*)(Wq + c * D + lane * 4);
                p[j] = wv.x * tg.x + wv.y * tg.y + wv.z * tg.z + wv.w * tg.w;
            }
#pragma unroll
            for (int o = 16; o; o >>= 1)
#pragma unroll
                for (int j = 0; j < 8; j++)
                    p[j] += __shfl_xor_sync(0xffffffffu, p[j], o);
            if (lane == 0) {
#pragma unroll
                for (int j = 0; j < 8; j++) q_s[wid * 32 + cb + j] = p[j];
            }
        }
    } else {
        // tv[e] = sum_c tgt[c]*Wv[c,e]  (coalesced column reads)
        int e = tid - 128;
        float acc = 0.f;
#pragma unroll 8
        for (int c = 0; c < D; c++) acc += tgt_s[c] * Wv[c * D + e];
        tv_s[e] = acc;
    }
    __syncthreads();

    // ---- phase 2: tensor-core GEMM  k[r][c] = sum_e A[r][e]*Wk[c][e] -----
    {
        uint32_t as_base = (uint32_t)__cvta_generic_to_shared(As);
        uint32_t wk_base = (uint32_t)__cvta_generic_to_shared(Wkb);
        // 26 units: unit u = mtile*2 + nhalf; each unit = 16 rows x 64 cols
        for (int u = wid; u < 26; u += 8) {
            int m0 = (u >> 1) * 16;
            int nb = (u & 1) * 64;
            float c[8][4];
#pragma unroll
            for (int i = 0; i < 8; i++)
#pragma unroll
                for (int j = 0; j < 4; j++) c[i][j] = 0.f;

            uint32_t a_addr0 = as_base +
                ((m0 + (lane & 15)) * ASD + ((lane >> 4) << 3)) * 2;
#pragma unroll
            for (int ks = 0; ks < 8; ks++) {
                int k0 = ks * 16;
                unsigned a0, a1, a2, a3;
                ldsm4(a0, a1, a2, a3, a_addr0 + k0 * 2);
#pragma unroll
                for (int p = 0; p < 4; p++) {
                    int n0 = nb + p * 16;
                    uint32_t b_addr = wk_base +
                        ((n0 + (lane & 7) + ((lane >> 4) << 3)) * WKD +
                         k0 + (((lane >> 3) & 1) << 3)) * 2;
                    unsigned b0, b1, b2, b3;
                    ldsm4(b0, b1, b2, b3, b_addr);
                    mma16816(c[2 * p],     a0, a1, a2, a3, b0, b1);
                    mma16816(c[2 * p + 1], a0, a1, a2, a3, b2, b3);
                }
            }
            int row = m0 + (lane >> 2);
            int colb = (lane & 3) << 1;
#pragma unroll
            for (int p = 0; p < 4; p++) {
#pragma unroll
                for (int q = 0; q < 2; q++) {
                    float* cc = c[2 * p + q];
                    int col = nb + p * 16 + q * 8 + colb;
                    *(__nv_bfloat162*)&kb[row * KBD + col] =
                        __floats2bfloat162_rn(cc[0], cc[1]);
                    *(__nv_bfloat162*)&kb[(row + 8) * KBD + col] =
                        __floats2bfloat162_rn(cc[2], cc[3]);
                }
            }
        }
    }
    __syncthreads();

    // ---- phase 3: scores via faithful reshape, masked exp ----------------
    // scores[i] = sum_x q[x] * kflat[200x+i],  kflat j=r*128+c -> kb[r][c]
    float me = 0.f;
    if (tid < H) {
        float sc = 0.f;
        int j = tid;
#pragma unroll 8
        for (int x = 0; x < D; x++) {
            int rr = j >> 7, cc = j & 127;
            sc += q_s[x] * __bfloat162float(kb[rr * KBD + cc]);
            j += H;
        }
        sc *= 0.088388347648318447f;                 // 1/sqrt(128)
        me = (hidx_s[tid] != tgt_i) ? expf(sc) : 0.f;
    }
    float S = block_sum(me, red);

    // ---- phase 4: attn + geo + bilinear reduction ------------------------
    float contrib = 0.f;
    if (tid < H) {
        float attn = me / sqrtf(S);                  // exp_sum ** 0.5
        float geo  = expf(g_geo[tid] * dist[b * H + tid]);
        float w    = attn + geo;
        float dv = 0.f, dt = 0.f;
        const __nv_bfloat16* arow = As + tid * ASD;
#pragma unroll 8
        for (int e = 0; e < D; e += 4) {
            float4 tvv = *(const float4*)&tv_s[e];
            float4 tgg = *(const float4*)&tgt_s[e];
            __nv_bfloat162 p0 = *(const __nv_bfloat162*)&arow[e];
            __nv_bfloat162 p1 = *(const __nv_bfloat162*)&arow[e + 2];
            float a0 = __bfloat162float(p0.x), a1 = __bfloat162float(p0.y);
            float a2 = __bfloat162float(p1.x), a3 = __bfloat162float(p1.y);
            dv += a0 * tvv.x + a1 * tvv.y + a2 * tvv.z + a3 * tvv.w;
            dt += a0 * tgg.x + a1 * tgg.y + a2 * tgg.z + a3 * tgg.w;
        }
        contrib = w * dv + hv[tid] * dt;
    }
    float pred = block_sum(contrib, red);
    if (tid == 0) out[b] = 1.0f / (1.0f + expf(-pred));
}

// ---------------------------------------------------------------------------
extern "C" void kernel_launch(void* const* d_in, const int* in_sizes, int n_in,
                              void* d_out, int out_size) {
    const int*   history = (const int*)  d_in[0];
    const int*   target  = (const int*)  d_in[1];
    const int*   hregion = (const int*)  d_in[2];
    const int*   tregion = (const int*)  d_in[3];
    const float* hv      = (const float*)d_in[4];
    const float* dist    = (const float*)d_in[5];
    const int*   uid     = (const int*)  d_in[6];
    const float* embT    = (const float*)d_in[7];
    const float* embR    = (const float*)d_in[8];
    const float* embD    = (const float*)d_in[9];
    const float* Wq      = (const float*)d_in[10];
    const float* Wk      = (const float*)d_in[11];
    const float* Wv      = (const float*)d_in[12];
    float*       out     = (float*)d_out;

    int b          = in_sizes[1];          // 1024
    int region_num = in_sizes[8] / 64;     // 1000

    cudaFuncSetAttribute(main_kernel, cudaFuncAttributeMaxDynamicSharedMemorySize,
                         SMEM_BYTES);

    geo_kernel<<<H, NT>>>(hregion, tregion, embD, uid, b, region_num);
    main_kernel<<<b, NT, SMEM_BYTES>>>(history, target, hregion, tregion,
                                       hv, dist, embT, embR, Wq, Wk, Wv, out);
}

// round 4
// speedup vs baseline: 3.3369x; 1.2744x over previous
#include <cuda_runtime.h>
#include <cuda_bf16.h>
#include <cstdint>

// Problem constants (fixed shapes)
#define H     200
#define D     128
#define NT    256
#define ASD   136     // As row stride (bf16, +8 pad: conflict-free ldmatrix)
#define WKD   136     // Wkb row stride
#define MROWS 208     // H padded to 13 m-tiles of 16

// smem layout (bytes)
#define OFF_AS   0
#define SZ_AS    (MROWS*ASD*2)            // 56576
#define OFF_WK   (OFF_AS + SZ_AS)
#define SZ_WK    (128*WKD*2)              // 34816
#define OFF_SC   (OFF_WK + SZ_WK)         // per-warp score partials [8][200] f32
#define SZ_SC    (8*H*4)                  // 6400
#define OFF_TGT  (OFF_SC + SZ_SC)
#define OFF_Q    (OFF_TGT + 512)
#define OFF_TV   (OFF_Q + 512)
#define OFF_HIDX (OFF_TV + 512)
#define OFF_HREG (OFF_HIDX + 800)
#define OFF_RED  (OFF_HREG + 800)
#define SMEM_BYTES (OFF_RED + 128)        // 101056  -> 2 CTAs/SM

__device__ float g_geo[1024];   // g[i] = -1/(relu(s_i)+1), batch-independent

// ---------------------------------------------------------------------------
// Kernel 1: cross-batch geo reduction.  s[j] = sum_b erow[tr[b]] * erow[hr[b,j]]
// ---------------------------------------------------------------------------
__global__ void geo_kernel(const int* __restrict__ hr, const int* __restrict__ tr,
                           const float* __restrict__ embD, const int* __restrict__ uidp,
                           int b, int region_num) {
    __shared__ float red[8];
    const float* erow = embD + (size_t)uidp[0] * (size_t)region_num;
    int j = blockIdx.x;
    float s = 0.f;
    for (int bb = threadIdx.x; bb < b; bb += blockDim.x)
        s += erow[tr[bb]] * erow[hr[bb * H + j]];
    int lane = threadIdx.x & 31, w = threadIdx.x >> 5;
#pragma unroll
    for (int o = 16; o; o >>= 1) s += __shfl_down_sync(0xffffffffu, s, o);
    if (lane == 0) red[w] = s;
    __syncthreads();
    if (threadIdx.x == 0) {
        float t = 0.f;
#pragma unroll
        for (int i = 0; i < 8; i++) t += red[i];
        g_geo[j] = -1.0f / (fmaxf(t, 0.f) + 1.0f);
    }
}

// ---------------------------------------------------------------------------
__device__ __forceinline__ float block_sum(float v, float* red) {
    int lane = threadIdx.x & 31, w = threadIdx.x >> 5;
#pragma unroll
    for (int o = 16; o; o >>= 1) v += __shfl_down_sync(0xffffffffu, v, o);
    __syncthreads();
    if (lane == 0) red[w] = v;
    __syncthreads();
    float s = (threadIdx.x < 8) ? red[threadIdx.x] : 0.f;
    if (w == 0) {
#pragma unroll
        for (int o = 4; o; o >>= 1) s += __shfl_down_sync(0xffffffffu, s, o);
        if (lane == 0) red[0] = s;
    }
    __syncthreads();
    return red[0];
}

__device__ __forceinline__ void ldsm4(unsigned& r0, unsigned& r1, unsigned& r2,
                                      unsigned& r3, uint32_t addr) {
    asm volatile("ldmatrix.sync.aligned.m8n8.x4.shared.b16 {%0,%1,%2,%3}, [%4];\n"
                 : "=r"(r0), "=r"(r1), "=r"(r2), "=r"(r3) : "r"(addr));
}

__device__ __forceinline__ void mma16816(float* c, unsigned a0, unsigned a1,
                                         unsigned a2, unsigned a3,
                                         unsigned b0, unsigned b1) {
    asm volatile("mma.sync.aligned.m16n8k16.row.col.f32.bf16.bf16.f32 "
                 "{%0,%1,%2,%3}, {%4,%5,%6,%7}, {%8,%9}, {%0,%1,%2,%3};\n"
                 : "+f"(c[0]), "+f"(c[1]), "+f"(c[2]), "+f"(c[3])
                 : "r"(a0), "r"(a1), "r"(a2), "r"(a3), "r"(b0), "r"(b1));
}

// ---------------------------------------------------------------------------
// Kernel 2: one CTA per batch element, 2 CTAs/SM.
// ---------------------------------------------------------------------------
__global__ __launch_bounds__(NT, 2)
void main_kernel(const int* __restrict__ history, const int* __restrict__ target,
                 const int* __restrict__ hregion, const int* __restrict__ tregion,
                 const float* __restrict__ hv, const float* __restrict__ dist,
                 const float* __restrict__ embT, const float* __restrict__ embR,
                 const float* __restrict__ Wq, const float* __restrict__ Wk,
                 const float* __restrict__ Wv, float* __restrict__ out) {
    extern __shared__ char smem[];
    __nv_bfloat16* As   = (__nv_bfloat16*)(smem + OFF_AS);   // [208][136]
    __nv_bfloat16* Wkb  = (__nv_bfloat16*)(smem + OFF_WK);   // [128][136]
    float* sw     = (float*)(smem + OFF_SC);                 // [8][200]
    float* tgt_s  = (float*)(smem + OFF_TGT);
    float* q_s    = (float*)(smem + OFF_Q);                  // pre-scaled by 1/sqrt(128)
    float* tv_s   = (float*)(smem + OFF_TV);
    int*   hidx_s = (int*)(smem + OFF_HIDX);
    int*   hreg_s = (int*)(smem + OFF_HREG);
    float* red    = (float*)(smem + OFF_RED);

    const int b    = blockIdx.x;
    const int tid  = threadIdx.x;
    const int wid  = tid >> 5, lane = tid & 31;
    const int tgt_i  = target[b];
    const int treg_i = tregion[b];

    // ---- phase 0: indices + target embedding (fp32) ----------------------
    for (int r = tid; r < H; r += NT) {
        hidx_s[r] = history[b * H + r];
        hreg_s[r] = hregion[b * H + r];
    }
    if (tid < D)
        tgt_s[tid] = (tid < 64) ? embT[(size_t)tgt_i * 64 + tid]
                                : embR[(size_t)treg_i * 64 + (tid - 64)];
    // zero per-warp score partials
    for (int i = tid; i < 8 * H; i += NT) sw[i] = 0.f;
    __syncthreads();

    // ---- phase 1: stage Wk (bf16), gather A (bf16), compute q & tv -------
    for (int i2 = tid; i2 < 8192; i2 += NT) {               // Wk -> smem bf16
        int c = i2 >> 6, e2 = (i2 & 63) << 1;
        float2 v = *(const float2*)(Wk + c * D + e2);
        *(__nv_bfloat162*)&Wkb[c * WKD + e2] = __floats2bfloat162_rn(v.x, v.y);
    }
    for (int i2 = tid; i2 < 12800; i2 += NT) {              // gather hist_emb
        int r = i2 >> 6, ep = (i2 & 63) << 1;
        const float* src = (ep < 64) ? (embT + (size_t)hidx_s[r] * 64 + ep)
                                     : (embR + (size_t)hreg_s[r] * 64 + (ep - 64));
        float2 v = *(const float2*)src;
        *(__nv_bfloat162*)&As[r * ASD + ep] = __floats2bfloat162_rn(v.x, v.y);
    }
    for (int i = tid; i < 512; i += NT) {                   // zero pad rows
        int r = 200 + (i >> 6), ep = (i & 63) << 1;
        *(__nv_bfloat162*)&As[r * ASD + ep] = __floats2bfloat162_rn(0.f, 0.f);
    }
    if (wid < 4) {
        // q[c] = (1/sqrt(128)) * sum_e tgt[e]*Wq[c,e]
        float4 tg = *(const float4*)&tgt_s[lane * 4];
        for (int cb = 0; cb < 32; cb += 8) {
            float p[8];
#pragma unroll
            for (int j = 0; j < 8; j++) {
                int c = wid * 32 + cb + j;
                float4 wv = *(const float4*)(Wq + c * D + lane * 4);
                p[j] = wv.x * tg.x + wv.y * tg.y + wv.z * tg.z + wv.w * tg.w;
            }
#pragma unroll
            for (int o = 16; o; o >>= 1)
#pragma unroll
                for (int j = 0; j < 8; j++)
                    p[j] += __shfl_xor_sync(0xffffffffu, p[j], o);
            if (lane == 0) {
#pragma unroll
                for (int j = 0; j < 8; j++)
                    q_s[wid * 32 + cb + j] = p[j] * 0.088388347648318447f;
            }
        }
    } else {
        // tv[e] = sum_c tgt[c]*Wv[c,e]  (coalesced column reads)
        int e = tid - 128;
        float acc = 0.f;
#pragma unroll 8
        for (int c = 0; c < D; c++) acc += tgt_s[c] * Wv[c * D + e];
        tv_s[e] = acc;
    }
    __syncthreads();

    // ---- phase 2: tensor-core GEMM with fused score epilogue -------------
    // k[r][c] = sum_e A[r][e]*Wk[c][e];  element (r,c) with j=r*128+c adds
    // q[j/200]*k into sw[wid][j%200]  (no kb materialization).
    {
        uint32_t as_base = (uint32_t)__cvta_generic_to_shared(As);
        uint32_t wk_base = (uint32_t)__cvta_generic_to_shared(Wkb);
        float* swp = sw + wid * H;
        for (int u = wid; u < 26; u += 8) {
            int m0 = (u >> 1) * 16;
            int nb = (u & 1) * 64;
            float c[8][4];
#pragma unroll
            for (int i = 0; i < 8; i++)
#pragma unroll
                for (int j = 0; j < 4; j++) c[i][j] = 0.f;

            uint32_t a_addr0 = as_base +
                ((m0 + (lane & 15)) * ASD + ((lane >> 4) << 3)) * 2;
#pragma unroll
            for (int ks = 0; ks < 8; ks++) {
                int k0 = ks * 16;
                unsigned a0, a1, a2, a3;
                ldsm4(a0, a1, a2, a3, a_addr0 + k0 * 2);
#pragma unroll
                for (int p = 0; p < 4; p++) {
                    int n0 = nb + p * 16;
                    uint32_t b_addr = wk_base +
                        ((n0 + (lane & 7) + ((lane >> 4) << 3)) * WKD +
                         k0 + (((lane >> 3) & 1) << 3)) * 2;
                    unsigned b0, b1, b2, b3;
                    ldsm4(b0, b1, b2, b3, b_addr);
                    mma16816(c[2 * p],     a0, a1, a2, a3, b0, b1);
                    mma16816(c[2 * p + 1], a0, a1, a2, a3, b2, b3);
                }
            }
            // fused epilogue: scatter-accumulate into this warp's partials.
            // Within any accumulator tile no two lanes share (j % 200), so
            // plain smem RMW is race-free for the warp.
            int row0 = m0 + (lane >> 2);
            int colb = (lane & 3) << 1;
#pragma unroll
            for (int p = 0; p < 4; p++) {
#pragma unroll
                for (int q = 0; q < 2; q++) {
                    float* cc = c[2 * p + q];
                    int col = nb + p * 16 + q * 8 + colb;
#pragma unroll
                    for (int hh = 0; hh < 2; hh++) {      // row0, row0+8
                        int r = row0 + hh * 8;
                        if (r < H) {
                            int j0 = r * 128 + col;
                            swp[j0 % H]       += q_s[j0 / H]       * cc[2 * hh];
                            swp[(j0 + 1) % H] += q_s[(j0 + 1) / H] * cc[2 * hh + 1];
                        }
                    }
                }
            }
        }
    }
    __syncthreads();

    // ---- phase 3: reduce warp partials, masked exp ------------------------
    float me = 0.f;
    if (tid < H) {
        float sc = 0.f;
#pragma unroll
        for (int w = 0; w < 8; w++) sc += sw[w * H + tid];
        me = (hidx_s[tid] != tgt_i) ? expf(sc) : 0.f;
    }
    float S = block_sum(me, red);

    // ---- phase 4: attn + geo + bilinear reduction ------------------------
    float contrib = 0.f;
    if (tid < H) {
        float attn = me / sqrtf(S);                  // exp_sum ** 0.5
        float geo  = expf(g_geo[tid] * dist[b * H + tid]);
        float w    = attn + geo;
        float dv = 0.f, dt = 0.f;
        const __nv_bfloat16* arow = As + tid * ASD;
#pragma unroll 8
        for (int e = 0; e < D; e += 4) {
            float4 tvv = *(const float4*)&tv_s[e];
            float4 tgg = *(const float4*)&tgt_s[e];
            __nv_bfloat162 p0 = *(const __nv_bfloat162*)&arow[e];
            __nv_bfloat162 p1 = *(const __nv_bfloat162*)&arow[e + 2];
            float a0 = __bfloat162float(p0.x), a1 = __bfloat162float(p0.y);
            float a2 = __bfloat162float(p1.x), a3 = __bfloat162float(p1.y);
            dv += a0 * tvv.x + a1 * tvv.y + a2 * tvv.z + a3 * tvv.w;
            dt += a0 * tgg.x + a1 * tgg.y + a2 * tgg.z + a3 * tgg.w;
        }
        contrib = w * dv + hv[tid] * dt;
    }
    float pred = block_sum(contrib, red);
    if (tid == 0) out[b] = 1.0f / (1.0f + expf(-pred));
}

// ---------------------------------------------------------------------------
extern "C" void kernel_launch(void* const* d_in, const int* in_sizes, int n_in,
                              void* d_out, int out_size) {
    const int*   history = (const int*)  d_in[0];
    const int*   target  = (const int*)  d_in[1];
    const int*   hregion = (const int*)  d_in[2];
    const int*   tregion = (const int*)  d_in[3];
    const float* hv      = (const float*)d_in[4];
    const float* dist    = (const float*)d_in[5];
    const int*   uid     = (const int*)  d_in[6];
    const float* embT    = (const float*)d_in[7];
    const float* embR    = (const float*)d_in[8];
    const float* embD    = (const float*)d_in[9];
    const float* Wq      = (const float*)d_in[10];
    const float* Wk      = (const float*)d_in[11];
    const float* Wv      = (const float*)d_in[12];
    float*       out     = (float*)d_out;

    int b          = in_sizes[1];          // 1024
    int region_num = in_sizes[8] / 64;     // 1000

    cudaFuncSetAttribute(main_kernel, cudaFuncAttributeMaxDynamicSharedMemorySize,
                         SMEM_BYTES);

    geo_kernel<<<H, NT>>>(hregion, tregion, embD, uid, b, region_num);
    main_kernel<<<b, NT, SMEM_BYTES>>>(history, target, hregion, tregion,
                                       hv, dist, embT, embR, Wq, Wk, Wv, out);
}

// round 11
// speedup vs baseline: 4.1329x; 1.2385x over previous
#include <cuda_runtime.h>
#include <cuda_bf16.h>
#include <cstdint>

// Problem constants (fixed shapes)
#define H     200
#define D     128
#define NT    256
#define ASD   136        // row stride (bf16) for A and Wk tiles (+8 pad)
#define MROWS 208        // H padded to 13 m-tiles of 16
#define ABSTR (MROWS*ASD)        // 28288 elems per batch in g_Ab
#define AS_BYTES (MROWS*ASD*2)   // 56576
#define WK_BYTES (128*ASD*2)     // 34816
#define CH_AS (AS_BYTES/16)      // 3536 16B chunks
#define CH_WK (WK_BYTES/16)      // 2176

// main kernel smem layout
#define OFF_AS   0
#define OFF_WK   (OFF_AS + AS_BYTES)        // 56576
#define OFF_SC   (OFF_WK + WK_BYTES)        // 91392  [8][200] f32
#define OFF_Q    (OFF_SC + 8*H*4)           // 97792
#define OFF_TV   (OFF_Q + 512)              // 98304
#define OFF_TGT  (OFF_TV + 512)             // 98816
#define OFF_RED  (OFF_TGT + 512)            // 99328
#define SMEM_BYTES (OFF_RED + 128)          // 99456 -> 2 CTAs/SM

__device__ __align__(16) float          g_geo[1024];
__device__ __align__(16) __nv_bfloat16  g_Wkb[128 * ASD];    // Wk bf16, padded
__device__ __align__(16) __nv_bfloat16  g_Ab[1024 * ABSTR];  // gathered A bf16
__device__ __align__(16) float          g_q[1024 * D];       // pre-scaled
__device__ __align__(16) float          g_tv[1024 * D];
__device__ __align__(16) float          g_tgt[1024 * D];

// ---------------------------------------------------------------------------
__device__ __forceinline__ void cp16(uint32_t dst, const void* src) {
    asm volatile("cp.async.cg.shared.global [%0], [%1], 16;\n"
                 :: "r"(dst), "l"(src));
}
__device__ __forceinline__ void ldsm4(unsigned& r0, unsigned& r1, unsigned& r2,
                                      unsigned& r3, uint32_t addr) {
    asm volatile("ldmatrix.sync.aligned.m8n8.x4.shared.b16 {%0,%1,%2,%3}, [%4];\n"
                 : "=r"(r0), "=r"(r1), "=r"(r2), "=r"(r3) : "r"(addr));
}
__device__ __forceinline__ void mma16816(float* c, unsigned a0, unsigned a1,
                                         unsigned a2, unsigned a3,
                                         unsigned b0, unsigned b1) {
    asm volatile("mma.sync.aligned.m16n8k16.row.col.f32.bf16.bf16.f32 "
                 "{%0,%1,%2,%3}, {%4,%5,%6,%7}, {%8,%9}, {%0,%1,%2,%3};\n"
                 : "+f"(c[0]), "+f"(c[1]), "+f"(c[2]), "+f"(c[3])
                 : "r"(a0), "r"(a1), "r"(a2), "r"(a3), "r"(b0), "r"(b1));
}
__device__ __forceinline__ unsigned bf2_as_u32(__nv_bfloat162 v) {
    unsigned u;
    memcpy(&u, &v, 4);
    return u;
}

// ---------------------------------------------------------------------------
// Prep 1: Wk fp32 -> bf16 padded layout (once, not per CTA)
// ---------------------------------------------------------------------------
__global__ void wkb_kernel(const float* __restrict__ Wk) {
    int i2 = blockIdx.x * 256 + threadIdx.x;          // 8192 float2 slots
    if (i2 < 8192) {
        int c = i2 >> 6, e2 = (i2 & 63) << 1;
        float2 v = *(const float2*)(Wk + c * D + e2);
        *(__nv_bfloat162*)&g_Wkb[c * ASD + e2] = __floats2bfloat162_rn(v.x, v.y);
    }
}

// ---------------------------------------------------------------------------
// Prep 2: q = (tgt_emb @ WqT)/sqrt(d), tv = tgt_emb @ Wv, tgt_emb itself.
// 4 batches per CTA (4x reuse of Wq/Wv loads).
// ---------------------------------------------------------------------------
__global__ __launch_bounds__(NT)
void qtv_kernel(const int* __restrict__ target, const int* __restrict__ tregion,
                const float* __restrict__ embT, const float* __restrict__ embR,
                const float* __restrict__ Wq, const float* __restrict__ Wv) {
    __shared__ float tgt4[4][D];
    const int b0 = blockIdx.x * 4;
    const int tid = threadIdx.x, wid = tid >> 5, lane = tid & 31;

    for (int i = tid; i < 4 * D; i += NT) {
        int j = i >> 7, e = i & 127, bb = b0 + j;
        int ti = target[bb], tr = tregion[bb];
        float v = (e < 64) ? embT[(size_t)ti * 64 + e]
                           : embR[(size_t)tr * 64 + (e - 64)];
        tgt4[j][e] = v;
        g_tgt[(size_t)bb * D + e] = v;
    }
    __syncthreads();

    if (wid < 4) {
        // q: warp wid handles c in [wid*32, wid*32+32)
        float4 tg[4];
#pragma unroll
        for (int j = 0; j < 4; j++) tg[j] = *(const float4*)&tgt4[j][lane * 4];
        for (int cb = 0; cb < 32; cb += 8) {
            float4 wv[8];
#pragma unroll
            for (int jj = 0; jj < 8; jj++)
                wv[jj] = *(const float4*)(Wq + (wid * 32 + cb + jj) * D + lane * 4);
#pragma unroll
            for (int j = 0; j < 4; j++) {
                float p[8];
#pragma unroll
                for (int jj = 0; jj < 8; jj++)
                    p[jj] = wv[jj].x * tg[j].x + wv[jj].y * tg[j].y +
                            wv[jj].z * tg[j].z + wv[jj].w * tg[j].w;
#pragma unroll
                for (int o = 16; o; o >>= 1)
#pragma unroll
                    for (int jj = 0; jj < 8; jj++)
                        p[jj] += __shfl_xor_sync(0xffffffffu, p[jj], o);
                if (lane == 0) {
#pragma unroll
                    for (int jj = 0; jj < 8; jj++)
                        g_q[(size_t)(b0 + j) * D + wid * 32 + cb + jj] =
                            p[jj] * 0.088388347648318447f;
                }
            }
        }
    } else {
        // tv[e] for 4 batches, coalesced column reads of Wv
        int e = tid - 128;
        float acc0 = 0.f, acc1 = 0.f, acc2 = 0.f, acc3 = 0.f;
#pragma unroll 4
        for (int c = 0; c < D; c++) {
            float w = Wv[c * D + e];
            acc0 += tgt4[0][c] * w;
            acc1 += tgt4[1][c] * w;
            acc2 += tgt4[2][c] * w;
            acc3 += tgt4[3][c] * w;
        }
        g_tv[(size_t)(b0 + 0) * D + e] = acc0;
        g_tv[(size_t)(b0 + 1) * D + e] = acc1;
        g_tv[(size_t)(b0 + 2) * D + e] = acc2;
        g_tv[(size_t)(b0 + 3) * D + e] = acc3;
    }
}

// ---------------------------------------------------------------------------
// Prep 3: gather history embeddings into bf16 MMA layout.
// 128 elems/row = 32 float4 chunks/row; 200 rows * 32 = 6400 chunks.
// ---------------------------------------------------------------------------
__global__ __launch_bounds__(NT)
void gather_kernel(const int* __restrict__ history, const int* __restrict__ hregion,
                   const float* __restrict__ embT, const float* __restrict__ embR) {
    __shared__ int hidx[H], hreg[H];
    const int b = blockIdx.x, tid = threadIdx.x;
    for (int r = tid; r < H; r += NT) {
        hidx[r] = history[b * H + r];
        hreg[r] = hregion[b * H + r];
    }
    __syncthreads();
    __nv_bfloat16* dst = g_Ab + (size_t)b * ABSTR;
    for (int i4 = tid; i4 < 6400; i4 += NT) {
        int r = i4 >> 5, e4 = (i4 & 31) << 2;          // FIXED: 32 chunks/row
        const float* src = (e4 < 64) ? (embT + (size_t)hidx[r] * 64 + e4)
                                     : (embR + (size_t)hreg[r] * 64 + (e4 - 64));
        float4 v = *(const float4*)src;
        uint2 pk;
        pk.x = bf2_as_u32(__floats2bfloat162_rn(v.x, v.y));
        pk.y = bf2_as_u32(__floats2bfloat162_rn(v.z, v.w));
        *(uint2*)&dst[r * ASD + e4] = pk;
    }
    for (int i = tid; i < 272; i += NT) {              // zero pad rows 200..207
        int r = 200 + i / 34, c4 = (i % 34) * 4;
        uint2 z = {0u, 0u};
        *(uint2*)&dst[r * ASD + c4] = z;
    }
}

// ---------------------------------------------------------------------------
// Prep 4: cross-batch geo reduction  s[j] = sum_b erow[tr[b]] * erow[hr[b,j]]
// ---------------------------------------------------------------------------
__global__ void geo_kernel(const int* __restrict__ hr, const int* __restrict__ tr,
                           const float* __restrict__ embD, const int* __restrict__ uidp,
                           int b, int region_num) {
    __shared__ float red[8];
    const float* erow = embD + (size_t)uidp[0] * (size_t)region_num;
    int j = blockIdx.x;
    float s = 0.f;
    for (int bb = threadIdx.x; bb < b; bb += blockDim.x)
        s += erow[tr[bb]] * erow[hr[bb * H + j]];
    int lane = threadIdx.x & 31, w = threadIdx.x >> 5;
#pragma unroll
    for (int o = 16; o; o >>= 1) s += __shfl_down_sync(0xffffffffu, s, o);
    if (lane == 0) red[w] = s;
    __syncthreads();
    if (threadIdx.x == 0) {
        float t = 0.f;
#pragma unroll
        for (int i = 0; i < 8; i++) t += red[i];
        g_geo[j] = -1.0f / (fmaxf(t, 0.f) + 1.0f);
    }
}

// ---------------------------------------------------------------------------
__device__ __forceinline__ float block_sum(float v, float* red) {
    int lane = threadIdx.x & 31, w = threadIdx.x >> 5;
#pragma unroll
    for (int o = 16; o; o >>= 1) v += __shfl_down_sync(0xffffffffu, v, o);
    __syncthreads();
    if (lane == 0) red[w] = v;
    __syncthreads();
    float s = (threadIdx.x < 8) ? red[threadIdx.x] : 0.f;
    if (w == 0) {
#pragma unroll
        for (int o = 4; o; o >>= 1) s += __shfl_down_sync(0xffffffffu, s, o);
        if (lane == 0) red[0] = s;
    }
    __syncthreads();
    return red[0];
}

// ---------------------------------------------------------------------------
// Main: one CTA per batch element, 2 CTAs/SM. cp.async fill -> MMA GEMM with
// fused reshape-score epilogue -> attention/geo epilogue.
// ---------------------------------------------------------------------------
__global__ __launch_bounds__(NT, 2)
void main_kernel(const int* __restrict__ history, const int* __restrict__ target,
                 const float* __restrict__ hv, const float* __restrict__ dist,
                 float* __restrict__ out) {
    extern __shared__ char smem[];
    __nv_bfloat16* As  = (__nv_bfloat16*)(smem + OFF_AS);   // [208][136]
    __nv_bfloat16* Wkb = (__nv_bfloat16*)(smem + OFF_WK);   // [128][136]
    float* sw    = (float*)(smem + OFF_SC);                 // [8][200]
    float* q_s   = (float*)(smem + OFF_Q);
    float* tv_s  = (float*)(smem + OFF_TV);
    float* tgt_s = (float*)(smem + OFF_TGT);
    float* red   = (float*)(smem + OFF_RED);

    const int b   = blockIdx.x;
    const int tid = threadIdx.x;
    const int wid = tid >> 5, lane = tid & 31;
    const int tgt_i = target[b];

    // ---- phase A: async fill of all smem ---------------------------------
    {
        uint32_t as_u = (uint32_t)__cvta_generic_to_shared(As);
        const char* ab = (const char*)(g_Ab + (size_t)b * ABSTR);
        for (int i = tid; i < CH_AS; i += NT) cp16(as_u + i * 16, ab + i * 16);
        uint32_t wk_u = (uint32_t)__cvta_generic_to_shared(Wkb);
        const char* wk = (const char*)g_Wkb;
        for (int i = tid; i < CH_WK; i += NT) cp16(wk_u + i * 16, wk + i * 16);
        if (tid < 32) {
            uint32_t u = (uint32_t)__cvta_generic_to_shared(q_s);
            cp16(u + tid * 16, (const char*)(g_q + (size_t)b * D) + tid * 16);
        } else if (tid < 64) {
            int t = tid - 32;
            uint32_t u = (uint32_t)__cvta_generic_to_shared(tv_s);
            cp16(u + t * 16, (const char*)(g_tv + (size_t)b * D) + t * 16);
        } else if (tid < 96) {
            int t = tid - 64;
            uint32_t u = (uint32_t)__cvta_generic_to_shared(tgt_s);
            cp16(u + t * 16, (const char*)(g_tgt + (size_t)b * D) + t * 16);
        }
        for (int i = tid; i < 8 * H; i += NT) sw[i] = 0.f;   // zero partials
        asm volatile("cp.async.commit_group;\n" ::: "memory");
        asm volatile("cp.async.wait_group 0;\n" ::: "memory");
    }
    __syncthreads();

    // ---- phase B: tensor-core GEMM with fused score epilogue -------------
    // k[r][c] = sum_e A[r][e]*Wk[c][e]; element j=r*128+c adds q[j/200]*k
    // into sw[wid][j%200].
    {
        uint32_t as_base = (uint32_t)__cvta_generic_to_shared(As);
        uint32_t wk_base = (uint32_t)__cvta_generic_to_shared(Wkb);
        float* swp = sw + wid * H;
        for (int u = wid; u < 26; u += 8) {
            int m0 = (u >> 1) * 16;
            int nb = (u & 1) * 64;
            float c[8][4];
#pragma unroll
            for (int i = 0; i < 8; i++)
#pragma unroll
                for (int j = 0; j < 4; j++) c[i][j] = 0.f;

            uint32_t a_addr0 = as_base +
                ((m0 + (lane & 15)) * ASD + ((lane >> 4) << 3)) * 2;
#pragma unroll
            for (int ks = 0; ks < 8; ks++) {
                int k0 = ks * 16;
                unsigned a0, a1, a2, a3;
                ldsm4(a0, a1, a2, a3, a_addr0 + k0 * 2);
#pragma unroll
                for (int p = 0; p < 4; p++) {
                    int n0 = nb + p * 16;
                    uint32_t b_addr = wk_base +
                        ((n0 + (lane & 7) + ((lane >> 4) << 3)) * ASD +
                         k0 + (((lane >> 3) & 1) << 3)) * 2;
                    unsigned b0, b1, b2, b3;
                    ldsm4(b0, b1, b2, b3, b_addr);
                    mma16816(c[2 * p],     a0, a1, a2, a3, b0, b1);
                    mma16816(c[2 * p + 1], a0, a1, a2, a3, b2, b3);
                }
            }
            // fused epilogue: within a tile no two lanes share (j % 200),
            // so per-warp smem RMW is race-free.
            int row0 = m0 + (lane >> 2);
            int colb = (lane & 3) << 1;
#pragma unroll
            for (int p = 0; p < 4; p++) {
#pragma unroll
                for (int q = 0; q < 2; q++) {
                    float* cc = c[2 * p + q];
                    int col = nb + p * 16 + q * 8 + colb;
#pragma unroll
                    for (int hh = 0; hh < 2; hh++) {
                        int r = row0 + hh * 8;
                        if (r < H) {
                            int j0 = r * 128 + col;
                            swp[j0 % H]       += q_s[j0 / H]       * cc[2 * hh];
                            swp[(j0 + 1) % H] += q_s[(j0 + 1) / H] * cc[2 * hh + 1];
                        }
                    }
                }
            }
        }
    }
    __syncthreads();

    // ---- phase C: reduce partials, masked exp ----------------------------
    float me = 0.f;
    if (tid < H) {
        int hval = history[b * H + tid];
        float sc = 0.f;
#pragma unroll
        for (int w = 0; w < 8; w++) sc += sw[w * H + tid];
        me = (hval != tgt_i) ? expf(sc) : 0.f;
    }
    float S = block_sum(me, red);

    // ---- phase D: attn + geo + bilinear reduction ------------------------
    float contrib = 0.f;
    if (tid < H) {
        float attn = me / sqrtf(S);                  // exp_sum ** 0.5
        float geo  = expf(g_geo[tid] * dist[b * H + tid]);
        float w    = attn + geo;
        float dv = 0.f, dt = 0.f;
        const __nv_bfloat16* arow = As + tid * ASD;
#pragma unroll 8
        for (int e = 0; e < D; e += 4) {
            float4 tvv = *(const float4*)&tv_s[e];
            float4 tgg = *(const float4*)&tgt_s[e];
            __nv_bfloat162 p0 = *(const __nv_bfloat162*)&arow[e];
            __nv_bfloat162 p1 = *(const __nv_bfloat162*)&arow[e + 2];
            float a0 = __bfloat162float(p0.x), a1 = __bfloat162float(p0.y);
            float a2 = __bfloat162float(p1.x), a3 = __bfloat162float(p1.y);
            dv += a0 * tvv.x + a1 * tvv.y + a2 * tvv.z + a3 * tvv.w;
            dt += a0 * tgg.x + a1 * tgg.y + a2 * tgg.z + a3 * tgg.w;
        }
        contrib = w * dv + hv[tid] * dt;
    }
    float pred = block_sum(contrib, red);
    if (tid == 0) out[b] = 1.0f / (1.0f + expf(-pred));
}

// ---------------------------------------------------------------------------
extern "C" void kernel_launch(void* const* d_in, const int* in_sizes, int n_in,
                              void* d_out, int out_size) {
    const int*   history = (const int*)  d_in[0];
    const int*   target  = (const int*)  d_in[1];
    const int*   hregion = (const int*)  d_in[2];
    const int*   tregion = (const int*)  d_in[3];
    const float* hv      = (const float*)d_in[4];
    const float* dist    = (const float*)d_in[5];
    const int*   uid     = (const int*)  d_in[6];
    const float* embT    = (const float*)d_in[7];
    const float* embR    = (const float*)d_in[8];
    const float* embD    = (const float*)d_in[9];
    const float* Wq      = (const float*)d_in[10];
    const float* Wk      = (const float*)d_in[11];
    const float* Wv      = (const float*)d_in[12];
    float*       out     = (float*)d_out;

    int b          = in_sizes[1];          // 1024
    int region_num = in_sizes[8] / 64;     // 1000

    cudaFuncSetAttribute(main_kernel, cudaFuncAttributeMaxDynamicSharedMemorySize,
                         SMEM_BYTES);

    wkb_kernel<<<32, 256>>>(Wk);
    qtv_kernel<<<b / 4, NT>>>(target, tregion, embT, embR, Wq, Wv);
    gather_kernel<<<b, NT>>>(history, hregion, embT, embR);
    geo_kernel<<<H, NT>>>(hregion, tregion, embD, uid, b, region_num);
    main_kernel<<<b, NT, SMEM_BYTES>>>(history, target, hv, dist, out);
}

// round 13
// speedup vs baseline: 4.2956x; 1.0394x over previous
#include <cuda_runtime.h>
#include <cuda_bf16.h>
#include <cstdint>

// Problem constants (fixed shapes)
#define H     200
#define D     128
#define NT    256
#define ASD   136        // row stride (bf16) for A and Wk tiles (+8 pad)
#define MROWS 208        // H padded to 13 m-tiles of 16
#define ABSTR (MROWS*ASD)        // 28288 elems per batch in g_Ab
#define AS_BYTES (MROWS*ASD*2)   // 56576
#define WK_BYTES (128*ASD*2)     // 34816
#define CH_AS (AS_BYTES/16)      // 3536 16B chunks
#define CH_WK (WK_BYTES/16)      // 2176

// main kernel smem layout (all 16B aligned)
#define OFF_AS   0
#define OFF_WK   (OFF_AS + AS_BYTES)        // 56576
#define OFF_SC   (OFF_WK + WK_BYTES)        // 91392  [8][200] f32
#define OFF_Q    (OFF_SC + 8*H*4)           // 97792
#define OFF_DV   (OFF_Q + 512)              // 98304
#define OFF_DT   (OFF_DV + 800)             // 99104
#define OFF_HIST (OFF_DT + 800)             // 99904
#define OFF_DIST (OFF_HIST + 800)           // 100704
#define OFF_HV   (OFF_DIST + 800)           // 101504
#define OFF_RED  (OFF_HV + 800)             // 102304
#define SMEM_BYTES (OFF_RED + 128)          // 102432 -> 2 CTAs/SM

__device__ __align__(16) float          g_geo[1024];
__device__ __align__(16) __nv_bfloat16  g_Wkb[128 * ASD];    // Wk bf16, padded
__device__ __align__(16) __nv_bfloat16  g_Ab[1024 * ABSTR];  // gathered A bf16
__device__ __align__(16) float          g_q[1024 * D];       // pre-scaled
__device__ __align__(16) float          g_tv[1024 * D];
__device__ __align__(16) float          g_tgt[1024 * D];
__device__ __align__(16) float          g_dv[1024 * H];      // hist_i . tv
__device__ __align__(16) float          g_dt[1024 * H];      // hist_i . tgt

// ---------------------------------------------------------------------------
__device__ __forceinline__ void cp16(uint32_t dst, const void* src) {
    asm volatile("cp.async.cg.shared.global [%0], [%1], 16;\n"
                 :: "r"(dst), "l"(src));
}
__device__ __forceinline__ void ldsm4(unsigned& r0, unsigned& r1, unsigned& r2,
                                      unsigned& r3, uint32_t addr) {
    asm volatile("ldmatrix.sync.aligned.m8n8.x4.shared.b16 {%0,%1,%2,%3}, [%4];\n"
                 : "=r"(r0), "=r"(r1), "=r"(r2), "=r"(r3) : "r"(addr));
}
__device__ __forceinline__ void mma16816(float* c, unsigned a0, unsigned a1,
                                         unsigned a2, unsigned a3,
                                         unsigned b0, unsigned b1) {
    asm volatile("mma.sync.aligned.m16n8k16.row.col.f32.bf16.bf16.f32 "
                 "{%0,%1,%2,%3}, {%4,%5,%6,%7}, {%8,%9}, {%0,%1,%2,%3};\n"
                 : "+f"(c[0]), "+f"(c[1]), "+f"(c[2]), "+f"(c[3])
                 : "r"(a0), "r"(a1), "r"(a2), "r"(a3), "r"(b0), "r"(b1));
}
__device__ __forceinline__ unsigned bf2_as_u32(__nv_bfloat162 v) {
    unsigned u;
    memcpy(&u, &v, 4);
    return u;
}

// ---------------------------------------------------------------------------
// Prep 1 (fused): blocks 0-255 qtv | 256-287 Wk->bf16 | 288-487 geo.
// ---------------------------------------------------------------------------
__global__ __launch_bounds__(NT)
void prep1_kernel(const int* __restrict__ target, const int* __restrict__ tregion,
                  const float* __restrict__ embT, const float* __restrict__ embR,
                  const float* __restrict__ Wq, const float* __restrict__ Wv,
                  const float* __restrict__ Wk,
                  const int* __restrict__ hregion, const float* __restrict__ embD,
                  const int* __restrict__ uidp, int b, int region_num) {
    __shared__ float tgt4[4][D];
    __shared__ float red[8];
    const int blk = blockIdx.x;
    const int tid = threadIdx.x, wid = tid >> 5, lane = tid & 31;

    if (blk < 256) {
        // ---- qtv role: q, tv, tgt for 4 batches --------------------------
        const int b0 = blk * 4;
        for (int i = tid; i < 4 * D; i += NT) {
            int j = i >> 7, e = i & 127, bb = b0 + j;
            int ti = target[bb], tr = tregion[bb];
            float v = (e < 64) ? embT[(size_t)ti * 64 + e]
                               : embR[(size_t)tr * 64 + (e - 64)];
            tgt4[j][e] = v;
            g_tgt[(size_t)bb * D + e] = v;
        }
        __syncthreads();

        if (wid < 4) {
            float4 tg[4];
#pragma unroll
            for (int j = 0; j < 4; j++) tg[j] = *(const float4*)&tgt4[j][lane * 4];
            for (int cb = 0; cb < 32; cb += 8) {
                float4 wv[8];
#pragma unroll
                for (int jj = 0; jj < 8; jj++)
                    wv[jj] = *(const float4*)(Wq + (wid * 32 + cb + jj) * D + lane * 4);
#pragma unroll
                for (int j = 0; j < 4; j++) {
                    float p[8];
#pragma unroll
                    for (int jj = 0; jj < 8; jj++)
                        p[jj] = wv[jj].x * tg[j].x + wv[jj].y * tg[j].y +
                                wv[jj].z * tg[j].z + wv[jj].w * tg[j].w;
#pragma unroll
                    for (int o = 16; o; o >>= 1)
#pragma unroll
                        for (int jj = 0; jj < 8; jj++)
                            p[jj] += __shfl_xor_sync(0xffffffffu, p[jj], o);
                    if (lane == 0) {
#pragma unroll
                        for (int jj = 0; jj < 8; jj++)
                            g_q[(size_t)(b0 + j) * D + wid * 32 + cb + jj] =
                                p[jj] * 0.088388347648318447f;
                    }
                }
            }
        } else {
            int e = tid - 128;
            float acc0 = 0.f, acc1 = 0.f, acc2 = 0.f, acc3 = 0.f;
#pragma unroll 4
            for (int c = 0; c < D; c++) {
                float w = Wv[c * D + e];
                acc0 += tgt4[0][c] * w;
                acc1 += tgt4[1][c] * w;
                acc2 += tgt4[2][c] * w;
                acc3 += tgt4[3][c] * w;
            }
            g_tv[(size_t)(b0 + 0) * D + e] = acc0;
            g_tv[(size_t)(b0 + 1) * D + e] = acc1;
            g_tv[(size_t)(b0 + 2) * D + e] = acc2;
            g_tv[(size_t)(b0 + 3) * D + e] = acc3;
        }
    } else if (blk < 288) {
        // ---- wkb role: Wk fp32 -> bf16 padded ----------------------------
        int i2 = (blk - 256) * 256 + tid;
        if (i2 < 8192) {
            int c = i2 >> 6, e2 = (i2 & 63) << 1;
            float2 v = *(const float2*)(Wk + c * D + e2);
            *(__nv_bfloat162*)&g_Wkb[c * ASD + e2] =
                __floats2bfloat162_rn(v.x, v.y);
        }
    } else {
        // ---- geo role: s[j] = sum_b erow[tr[b]]*erow[hr[b,j]] ------------
        const float* erow = embD + (size_t)uidp[0] * (size_t)region_num;
        int j = blk - 288;
        float s = 0.f;
        for (int bb = tid; bb < b; bb += NT)
            s += erow[tregion[bb]] * erow[hregion[bb * H + j]];
#pragma unroll
        for (int o = 16; o; o >>= 1) s += __shfl_down_sync(0xffffffffu, s, o);
        if (lane == 0) red[wid] = s;
        __syncthreads();
        if (tid == 0) {
            float t = 0.f;
#pragma unroll
            for (int i = 0; i < 8; i++) t += red[i];
            g_geo[j] = -1.0f / (fmaxf(t, 0.f) + 1.0f);
        }
    }
}

// ---------------------------------------------------------------------------
// Prep 2: gather history embeddings into bf16 MMA layout AND compute
// dv[b,i] = hist_i . tv_b,  dt[b,i] = hist_i . tgt_b  (fp32, warp per row).
// ---------------------------------------------------------------------------
__global__ __launch_bounds__(NT)
void gather_kernel(const int* __restrict__ history, const int* __restrict__ hregion,
                   const float* __restrict__ embT, const float* __restrict__ embR) {
    __shared__ int hidx[H], hreg[H];
    __shared__ float tv_s[D], tgt_s[D];
    const int b = blockIdx.x, tid = threadIdx.x;
    const int wid = tid >> 5, lane = tid & 31;
    for (int r = tid; r < H; r += NT) {
        hidx[r] = history[b * H + r];
        hreg[r] = hregion[b * H + r];
    }
    if (tid < D) tv_s[tid] = g_tv[(size_t)b * D + tid];
    else if (tid < 2 * D) tgt_s[tid - D] = g_tgt[(size_t)b * D + (tid - D)];
    __syncthreads();

    __nv_bfloat16* dst = g_Ab + (size_t)b * ABSTR;
    const int e4 = lane * 4;
    const float4 tvv = *(const float4*)&tv_s[e4];
    const float4 tgg = *(const float4*)&tgt_s[e4];
    for (int r = wid; r < H; r += 8) {
        const float* src = (lane < 16) ? (embT + (size_t)hidx[r] * 64 + e4)
                                       : (embR + (size_t)hreg[r] * 64 + (e4 - 64));
        float4 v = *(const float4*)src;
        uint2 pk;
        pk.x = bf2_as_u32(__floats2bfloat162_rn(v.x, v.y));
        pk.y = bf2_as_u32(__floats2bfloat162_rn(v.z, v.w));
        *(uint2*)&dst[r * ASD + e4] = pk;
        float pdv = v.x * tvv.x + v.y * tvv.y + v.z * tvv.z + v.w * tvv.w;
        float pdt = v.x * tgg.x + v.y * tgg.y + v.z * tgg.z + v.w * tgg.w;
#pragma unroll
        for (int o = 16; o; o >>= 1) {
            pdv += __shfl_xor_sync(0xffffffffu, pdv, o);
            pdt += __shfl_xor_sync(0xffffffffu, pdt, o);
        }
        if (lane == 0) {
            g_dv[(size_t)b * H + r] = pdv;
            g_dt[(size_t)b * H + r] = pdt;
        }
    }
    for (int i = tid; i < 272; i += NT) {              // zero pad rows 200..207
        int r = 200 + i / 34, c4 = (i % 34) * 4;
        uint2 z = {0u, 0u};
        *(uint2*)&dst[r * ASD + c4] = z;
    }
}

// ---------------------------------------------------------------------------
__device__ __forceinline__ float block_sum(float v, float* red) {
    int lane = threadIdx.x & 31, w = threadIdx.x >> 5;
#pragma unroll
    for (int o = 16; o; o >>= 1) v += __shfl_down_sync(0xffffffffu, v, o);
    __syncthreads();
    if (lane == 0) red[w] = v;
    __syncthreads();
    float s = (threadIdx.x < 8) ? red[threadIdx.x] : 0.f;
    if (w == 0) {
#pragma unroll
        for (int o = 4; o; o >>= 1) s += __shfl_down_sync(0xffffffffu, s, o);
        if (lane == 0) red[0] = s;
    }
    __syncthreads();
    return red[0];
}

// ---------------------------------------------------------------------------
// Main: one CTA per batch element, 2 CTAs/SM. cp.async fill -> MMA GEMM with
// fused reshape-score epilogue -> light scalar epilogue (dv/dt precomputed).
// ---------------------------------------------------------------------------
__global__ __launch_bounds__(NT, 2)
void main_kernel(const int* __restrict__ history, const int* __restrict__ target,
                 const float* __restrict__ hv, const float* __restrict__ dist,
                 float* __restrict__ out) {
    extern __shared__ char smem[];
    __nv_bfloat16* As  = (__nv_bfloat16*)(smem + OFF_AS);   // [208][136]
    __nv_bfloat16* Wkb = (__nv_bfloat16*)(smem + OFF_WK);   // [128][136]
    float* sw     = (float*)(smem + OFF_SC);                // [8][200]
    float* q_s    = (float*)(smem + OFF_Q);
    float* dv_s   = (float*)(smem + OFF_DV);
    float* dt_s   = (float*)(smem + OFF_DT);
    int*   hist_s = (int*)(smem + OFF_HIST);
    float* dist_s = (float*)(smem + OFF_DIST);
    float* hv_s   = (float*)(smem + OFF_HV);
    float* red    = (float*)(smem + OFF_RED);

    const int b   = blockIdx.x;
    const int tid = threadIdx.x;
    const int wid = tid >> 5, lane = tid & 31;
    const int tgt_i = target[b];

    // ---- phase A: one async group fills ALL smem -------------------------
    {
        uint32_t as_u = (uint32_t)__cvta_generic_to_shared(As);
        const char* ab = (const char*)(g_Ab + (size_t)b * ABSTR);
        for (int i = tid; i < CH_AS; i += NT) cp16(as_u + i * 16, ab + i * 16);
        uint32_t wk_u = (uint32_t)__cvta_generic_to_shared(Wkb);
        const char* wk = (const char*)g_Wkb;
        for (int i = tid; i < CH_WK; i += NT) cp16(wk_u + i * 16, wk + i * 16);
        if (tid < 32) {
            uint32_t u = (uint32_t)__cvta_generic_to_shared(q_s);
            cp16(u + tid * 16, (const char*)(g_q + (size_t)b * D) + tid * 16);
        }
        if (tid < 50) {
            cp16((uint32_t)__cvta_generic_to_shared(dv_s) + tid * 16,
                 (const char*)(g_dv + (size_t)b * H) + tid * 16);
            cp16((uint32_t)__cvta_generic_to_shared(dt_s) + tid * 16,
                 (const char*)(g_dt + (size_t)b * H) + tid * 16);
            cp16((uint32_t)__cvta_generic_to_shared(hist_s) + tid * 16,
                 (const char*)(history + b * H) + tid * 16);
            cp16((uint32_t)__cvta_generic_to_shared(dist_s) + tid * 16,
                 (const char*)(dist + b * H) + tid * 16);
            cp16((uint32_t)__cvta_generic_to_shared(hv_s) + tid * 16,
                 (const char*)hv + tid * 16);
        }
        for (int i = tid; i < 8 * H; i += NT) sw[i] = 0.f;   // zero partials
        asm volatile("cp.async.commit_group;\n" ::: "memory");
        asm volatile("cp.async.wait_group 0;\n" ::: "memory");
    }
    __syncthreads();

    // ---- phase B: tensor-core GEMM with fused score epilogue -------------
    // k[r][c] = sum_e A[r][e]*Wk[c][e]; element j=r*128+c adds q[j/200]*k
    // into sw[wid][j%200].
    {
        uint32_t as_base = (uint32_t)__cvta_generic_to_shared(As);
        uint32_t wk_base = (uint32_t)__cvta_generic_to_shared(Wkb);
        float* swp = sw + wid * H;
        for (int u = wid; u < 26; u += 8) {
            int m0 = (u >> 1) * 16;
            int nb = (u & 1) * 64;
            float c[8][4];
#pragma unroll
            for (int i = 0; i < 8; i++)
#pragma unroll
                for (int j = 0; j < 4; j++) c[i][j] = 0.f;

            uint32_t a_addr0 = as_base +
                ((m0 + (lane & 15)) * ASD + ((lane >> 4) << 3)) * 2;
#pragma unroll
            for (int ks = 0; ks < 8; ks++) {
                int k0 = ks * 16;
                unsigned a0, a1, a2, a3;
                ldsm4(a0, a1, a2, a3, a_addr0 + k0 * 2);
#pragma unroll
                for (int p = 0; p < 4; p++) {
                    int n0 = nb + p * 16;
                    uint32_t b_addr = wk_base +
                        ((n0 + (lane & 7) + ((lane >> 4) << 3)) * ASD +
                         k0 + (((lane >> 3) & 1) << 3)) * 2;
                    unsigned b0, b1, b2, b3;
                    ldsm4(b0, b1, b2, b3, b_addr);
                    mma16816(c[2 * p],     a0, a1, a2, a3, b0, b1);
                    mma16816(c[2 * p + 1], a0, a1, a2, a3, b2, b3);
                }
            }
            // fused epilogue: within a tile no two lanes share (j % 200),
            // so per-warp smem RMW is race-free.
            int row0 = m0 + (lane >> 2);
            int colb = (lane & 3) << 1;
#pragma unroll
            for (int p = 0; p < 4; p++) {
#pragma unroll
                for (int q = 0; q < 2; q++) {
                    float* cc = c[2 * p + q];
                    int col = nb + p * 16 + q * 8 + colb;
#pragma unroll
                    for (int hh = 0; hh < 2; hh++) {
                        int r = row0 + hh * 8;
                        if (r < H) {
                            int j0 = r * 128 + col;
                            swp[j0 % H]       += q_s[j0 / H]       * cc[2 * hh];
                            swp[(j0 + 1) % H] += q_s[(j0 + 1) / H] * cc[2 * hh + 1];
                        }
                    }
                }
            }
        }
    }
    __syncthreads();

    // ---- phase C: reduce partials, masked exp ----------------------------
    float me = 0.f;
    if (tid < H) {
        float sc = 0.f;
#pragma unroll
        for (int w = 0; w < 8; w++) sc += sw[w * H + tid];
        me = (hist_s[tid] != tgt_i) ? __expf(sc) : 0.f;
    }
    float S = block_sum(me, red);

    // ---- phase D: attn + geo + precomputed bilinears ---------------------
    float contrib = 0.f;
    if (tid < H) {
        float attn = me / sqrtf(S);                  // exp_sum ** 0.5
        float geo  = __expf(g_geo[tid] * dist_s[tid]);
        contrib = (attn + geo) * dv_s[tid] + hv_s[tid] * dt_s[tid];
    }
    float pred = block_sum(contrib, red);
    if (tid == 0) out[b] = 1.0f / (1.0f + __expf(-pred));
}

// ---------------------------------------------------------------------------
extern "C" void kernel_launch(void* const* d_in, const int* in_sizes, int n_in,
                              void* d_out, int out_size) {
    const int*   history = (const int*)  d_in[0];
    const int*   target  = (const int*)  d_in[1];
    const int*   hregion = (const int*)  d_in[2];
    const int*   tregion = (const int*)  d_in[3];
    const float* hv      = (const float*)d_in[4];
    const float* dist    = (const float*)d_in[5];
    const int*   uid     = (const int*)  d_in[6];
    const float* embT    = (const float*)d_in[7];
    const float* embR    = (const float*)d_in[8];
    const float* embD    = (const float*)d_in[9];
    const float* Wq      = (const float*)d_in[10];
    const float* Wk      = (const float*)d_in[11];
    const float* Wv      = (const float*)d_in[12];
    float*       out     = (float*)d_out;

    int b          = in_sizes[1];          // 1024
    int region_num = in_sizes[8] / 64;     // 1000

    cudaFuncSetAttribute(main_kernel, cudaFuncAttributeMaxDynamicSharedMemorySize,
                         SMEM_BYTES);

    prep1_kernel<<<488, NT>>>(target, tregion, embT, embR, Wq, Wv, Wk,
                              hregion, embD, uid, b, region_num);
    gather_kernel<<<b, NT>>>(history, hregion, embT, embR);
    main_kernel<<<b, NT, SMEM_BYTES>>>(history, target, hv, dist, out);
}

// round 14
// speedup vs baseline: 4.5171x; 1.0516x over previous
#include <cuda_runtime.h>
#include <cuda_bf16.h>
#include <cstdint>

// Problem constants (fixed shapes)
#define H     200
#define D     128
#define NT    256
#define ASD   136        // row stride (bf16) for A and Wk tiles (+8 pad)
#define MROWS 208        // H padded to 13 m-tiles of 16
#define ABSTR (MROWS*ASD)        // 28288 elems per batch in g_Ab
#define WK_BYTES (128*ASD*2)     // 34816
#define CH_WK (WK_BYTES/16)      // 2176

// mainA smem layout (split kernel: 112 rows of A max)
#define A_OFF   0
#define A_SZ    (112*ASD*2)              // 30464
#define W_OFF   (A_OFF + A_SZ)           // 30464
#define SW_OFF  (W_OFF + WK_BYTES)       // 65280   [8][200] f32
#define Q_OFF   (SW_OFF + 8*H*4)         // 71680
#define SMEM_A_BYTES (Q_OFF + 512)       // 72192 -> 3 CTAs/SM (216.6KB)

__device__ __align__(16) float          g_geo[1024];
__device__ __align__(16) __nv_bfloat16  g_Wkb[128 * ASD];    // Wk bf16, padded
__device__ __align__(16) __nv_bfloat16  g_Ab[1024 * ABSTR];  // gathered A bf16
__device__ __align__(16) float          g_q[1024 * D];       // pre-scaled
__device__ __align__(16) float          g_tv[1024 * D];
__device__ __align__(16) float          g_tgt[1024 * D];
__device__ __align__(16) float          g_dv[1024 * H];      // hist_i . tv
__device__ __align__(16) float          g_dt[1024 * H];      // hist_i . tgt
__device__ __align__(16) float          g_swp[2048 * H];     // per-half scores

// ---------------------------------------------------------------------------
__device__ __forceinline__ void cp16(uint32_t dst, const void* src) {
    asm volatile("cp.async.cg.shared.global [%0], [%1], 16;\n"
                 :: "r"(dst), "l"(src));
}
__device__ __forceinline__ void ldsm4(unsigned& r0, unsigned& r1, unsigned& r2,
                                      unsigned& r3, uint32_t addr) {
    asm volatile("ldmatrix.sync.aligned.m8n8.x4.shared.b16 {%0,%1,%2,%3}, [%4];\n"
                 : "=r"(r0), "=r"(r1), "=r"(r2), "=r"(r3) : "r"(addr));
}
__device__ __forceinline__ void mma16816(float* c, unsigned a0, unsigned a1,
                                         unsigned a2, unsigned a3,
                                         unsigned b0, unsigned b1) {
    asm volatile("mma.sync.aligned.m16n8k16.row.col.f32.bf16.bf16.f32 "
                 "{%0,%1,%2,%3}, {%4,%5,%6,%7}, {%8,%9}, {%0,%1,%2,%3};\n"
                 : "+f"(c[0]), "+f"(c[1]), "+f"(c[2]), "+f"(c[3])
                 : "r"(a0), "r"(a1), "r"(a2), "r"(a3), "r"(b0), "r"(b1));
}
__device__ __forceinline__ unsigned bf2_as_u32(__nv_bfloat162 v) {
    unsigned u;
    memcpy(&u, &v, 4);
    return u;
}

// ---------------------------------------------------------------------------
// Prep 1 (fused): blocks 0-255 qtv | 256-287 Wk->bf16 | 288-487 geo.
// ---------------------------------------------------------------------------
__global__ __launch_bounds__(NT)
void prep1_kernel(const int* __restrict__ target, const int* __restrict__ tregion,
                  const float* __restrict__ embT, const float* __restrict__ embR,
                  const float* __restrict__ Wq, const float* __restrict__ Wv,
                  const float* __restrict__ Wk,
                  const int* __restrict__ hregion, const float* __restrict__ embD,
                  const int* __restrict__ uidp, int b, int region_num) {
    __shared__ float tgt4[4][D];
    __shared__ float red[8];
    const int blk = blockIdx.x;
    const int tid = threadIdx.x, wid = tid >> 5, lane = tid & 31;

    if (blk < 256) {
        const int b0 = blk * 4;
        for (int i = tid; i < 4 * D; i += NT) {
            int j = i >> 7, e = i & 127, bb = b0 + j;
            int ti = target[bb], tr = tregion[bb];
            float v = (e < 64) ? embT[(size_t)ti * 64 + e]
                               : embR[(size_t)tr * 64 + (e - 64)];
            tgt4[j][e] = v;
            g_tgt[(size_t)bb * D + e] = v;
        }
        __syncthreads();

        if (wid < 4) {
            float4 tg[4];
#pragma unroll
            for (int j = 0; j < 4; j++) tg[j] = *(const float4*)&tgt4[j][lane * 4];
            for (int cb = 0; cb < 32; cb += 8) {
                float4 wv[8];
#pragma unroll
                for (int jj = 0; jj < 8; jj++)
                    wv[jj] = *(const float4*)(Wq + (wid * 32 + cb + jj) * D + lane * 4);
#pragma unroll
                for (int j = 0; j < 4; j++) {
                    float p[8];
#pragma unroll
                    for (int jj = 0; jj < 8; jj++)
                        p[jj] = wv[jj].x * tg[j].x + wv[jj].y * tg[j].y +
                                wv[jj].z * tg[j].z + wv[jj].w * tg[j].w;
#pragma unroll
                    for (int o = 16; o; o >>= 1)
#pragma unroll
                        for (int jj = 0; jj < 8; jj++)
                            p[jj] += __shfl_xor_sync(0xffffffffu, p[jj], o);
                    if (lane == 0) {
#pragma unroll
                        for (int jj = 0; jj < 8; jj++)
                            g_q[(size_t)(b0 + j) * D + wid * 32 + cb + jj] =
                                p[jj] * 0.088388347648318447f;
                    }
                }
            }
        } else {
            int e = tid - 128;
            float acc0 = 0.f, acc1 = 0.f, acc2 = 0.f, acc3 = 0.f;
#pragma unroll 16
            for (int c = 0; c < D; c++) {
                float w = Wv[c * D + e];
                acc0 += tgt4[0][c] * w;
                acc1 += tgt4[1][c] * w;
                acc2 += tgt4[2][c] * w;
                acc3 += tgt4[3][c] * w;
            }
            g_tv[(size_t)(b0 + 0) * D + e] = acc0;
            g_tv[(size_t)(b0 + 1) * D + e] = acc1;
            g_tv[(size_t)(b0 + 2) * D + e] = acc2;
            g_tv[(size_t)(b0 + 3) * D + e] = acc3;
        }
    } else if (blk < 288) {
        int i2 = (blk - 256) * 256 + tid;
        if (i2 < 8192) {
            int c = i2 >> 6, e2 = (i2 & 63) << 1;
            float2 v = *(const float2*)(Wk + c * D + e2);
            *(__nv_bfloat162*)&g_Wkb[c * ASD + e2] =
                __floats2bfloat162_rn(v.x, v.y);
        }
    } else {
        const float* erow = embD + (size_t)uidp[0] * (size_t)region_num;
        int j = blk - 288;
        float s = 0.f;
        for (int bb = tid; bb < b; bb += NT)
            s += erow[tregion[bb]] * erow[hregion[bb * H + j]];
#pragma unroll
        for (int o = 16; o; o >>= 1) s += __shfl_down_sync(0xffffffffu, s, o);
        if (lane == 0) red[wid] = s;
        __syncthreads();
        if (tid == 0) {
            float t = 0.f;
#pragma unroll
            for (int i = 0; i < 8; i++) t += red[i];
            g_geo[j] = -1.0f / (fmaxf(t, 0.f) + 1.0f);
        }
    }
}

// ---------------------------------------------------------------------------
// Prep 2: gather hist embeddings into bf16 MMA layout + dv/dt bilinears.
// ---------------------------------------------------------------------------
__global__ __launch_bounds__(NT)
void gather_kernel(const int* __restrict__ history, const int* __restrict__ hregion,
                   const float* __restrict__ embT, const float* __restrict__ embR) {
    __shared__ int hidx[H], hreg[H];
    __shared__ float tv_s[D], tgt_s[D];
    const int b = blockIdx.x, tid = threadIdx.x;
    const int wid = tid >> 5, lane = tid & 31;
    for (int r = tid; r < H; r += NT) {
        hidx[r] = history[b * H + r];
        hreg[r] = hregion[b * H + r];
    }
    if (tid < D) tv_s[tid] = g_tv[(size_t)b * D + tid];
    else if (tid < 2 * D) tgt_s[tid - D] = g_tgt[(size_t)b * D + (tid - D)];
    __syncthreads();

    __nv_bfloat16* dst = g_Ab + (size_t)b * ABSTR;
    const int e4 = lane * 4;
    const float4 tvv = *(const float4*)&tv_s[e4];
    const float4 tgg = *(const float4*)&tgt_s[e4];
#pragma unroll 2
    for (int r = wid; r < H; r += 8) {
        const float* src = (lane < 16) ? (embT + (size_t)hidx[r] * 64 + e4)
                                       : (embR + (size_t)hreg[r] * 64 + (e4 - 64));
        float4 v = *(const float4*)src;
        uint2 pk;
        pk.x = bf2_as_u32(__floats2bfloat162_rn(v.x, v.y));
        pk.y = bf2_as_u32(__floats2bfloat162_rn(v.z, v.w));
        *(uint2*)&dst[r * ASD + e4] = pk;
        float pdv = v.x * tvv.x + v.y * tvv.y + v.z * tvv.z + v.w * tvv.w;
        float pdt = v.x * tgg.x + v.y * tgg.y + v.z * tgg.z + v.w * tgg.w;
#pragma unroll
        for (int o = 16; o; o >>= 1) {
            pdv += __shfl_xor_sync(0xffffffffu, pdv, o);
            pdt += __shfl_xor_sync(0xffffffffu, pdt, o);
        }
        if (lane == 0) {
            g_dv[(size_t)b * H + r] = pdv;
            g_dt[(size_t)b * H + r] = pdt;
        }
    }
    for (int i = tid; i < 272; i += NT) {              // zero pad rows 200..207
        int r = 200 + i / 34, c4 = (i % 34) * 4;
        uint2 z = {0u, 0u};
        *(uint2*)&dst[r * ASD + c4] = z;
    }
}

// ---------------------------------------------------------------------------
// Main A: 2 CTAs per batch (half = m-tile range), 3 CTAs/SM.
// cp.async fill -> MMA GEMM with fused reshape-score epilogue -> fold + STG.
// ---------------------------------------------------------------------------
__global__ __launch_bounds__(NT, 3)
void mainA_kernel() {
    extern __shared__ char smem[];
    __nv_bfloat16* As  = (__nv_bfloat16*)(smem + A_OFF);    // [<=112][136]
    __nv_bfloat16* Wkb = (__nv_bfloat16*)(smem + W_OFF);    // [128][136]
    float* sw  = (float*)(smem + SW_OFF);                   // [8][200]
    float* q_s = (float*)(smem + Q_OFF);

    const int bid  = blockIdx.x;
    const int b    = bid >> 1;
    const int half = bid & 1;
    const int row0 = half * 112;
    const int R    = half ? 96 : 112;     // rows this CTA owns (incl pad)
    const int T    = half ? 6 : 7;        // m-tiles
    const int tid  = threadIdx.x;
    const int wid  = tid >> 5, lane = tid & 31;

    // ---- phase A: async fill -------------------------------------------
    {
        uint32_t as_u = (uint32_t)__cvta_generic_to_shared(As);
        const char* ab = (const char*)(g_Ab + (size_t)b * ABSTR + row0 * ASD);
        const int nch = R * 17;                         // (ASD*2)/16 = 17
        for (int i = tid; i < nch; i += NT) cp16(as_u + i * 16, ab + i * 16);
        uint32_t wk_u = (uint32_t)__cvta_generic_to_shared(Wkb);
        const char* wk = (const char*)g_Wkb;
        for (int i = tid; i < CH_WK; i += NT) cp16(wk_u + i * 16, wk + i * 16);
        if (tid < 32) {
            uint32_t u = (uint32_t)__cvta_generic_to_shared(q_s);
            cp16(u + tid * 16, (const char*)(g_q + (size_t)b * D) + tid * 16);
        }
        for (int i = tid; i < 8 * H; i += NT) sw[i] = 0.f;
        asm volatile("cp.async.commit_group;\n" ::: "memory");
        asm volatile("cp.async.wait_group 0;\n" ::: "memory");
    }
    __syncthreads();

    // ---- phase B: GEMM + fused score epilogue ---------------------------
    {
        uint32_t as_base = (uint32_t)__cvta_generic_to_shared(As);
        uint32_t wk_base = (uint32_t)__cvta_generic_to_shared(Wkb);
        float* swp = sw + wid * H;
        for (int u = wid; u < 2 * T; u += 8) {
            int m0 = (u >> 1) * 16;                     // local row base
            int nb = (u & 1) * 64;
            float c[8][4];
#pragma unroll
            for (int i = 0; i < 8; i++)
#pragma unroll
                for (int j = 0; j < 4; j++) c[i][j] = 0.f;

            uint32_t a_addr0 = as_base +
                ((m0 + (lane & 15)) * ASD + ((lane >> 4) << 3)) * 2;
#pragma unroll
            for (int ks = 0; ks < 8; ks++) {
                int k0 = ks * 16;
                unsigned a0, a1, a2, a3;
                ldsm4(a0, a1, a2, a3, a_addr0 + k0 * 2);
#pragma unroll
                for (int p = 0; p < 4; p++) {
                    int n0 = nb + p * 16;
                    uint32_t b_addr = wk_base +
                        ((n0 + (lane & 7) + ((lane >> 4) << 3)) * ASD +
                         k0 + (((lane >> 3) & 1) << 3)) * 2;
                    unsigned b0, b1, b2, b3;
                    ldsm4(b0, b1, b2, b3, b_addr);
                    mma16816(c[2 * p],     a0, a1, a2, a3, b0, b1);
                    mma16816(c[2 * p + 1], a0, a1, a2, a3, b2, b3);
                }
            }
            // fused epilogue (per-instruction lane sets never collide mod 200)
            int lrow0 = m0 + (lane >> 2);
            int colb = (lane & 3) << 1;
#pragma unroll
            for (int p = 0; p < 4; p++) {
#pragma unroll
                for (int q = 0; q < 2; q++) {
                    float* cc = c[2 * p + q];
                    int col = nb + p * 16 + q * 8 + colb;
#pragma unroll
                    for (int hh = 0; hh < 2; hh++) {
                        int rg = row0 + lrow0 + hh * 8;  // global row
                        if (rg < H) {
                            int j0 = rg * 128 + col;
                            swp[j0 % H]       += q_s[j0 / H]       * cc[2 * hh];
                            swp[(j0 + 1) % H] += q_s[(j0 + 1) / H] * cc[2 * hh + 1];
                        }
                    }
                }
            }
        }
    }
    __syncthreads();

    // ---- phase C: fold 8 warp partials, store slice ---------------------
    if (tid < H) {
        float s = 0.f;
#pragma unroll
        for (int w = 0; w < 8; w++) s += sw[w * H + tid];
        g_swp[(size_t)bid * H + tid] = s;
    }
}

// ---------------------------------------------------------------------------
__device__ __forceinline__ float block_sum(float v, float* red) {
    int lane = threadIdx.x & 31, w = threadIdx.x >> 5;
#pragma unroll
    for (int o = 16; o; o >>= 1) v += __shfl_down_sync(0xffffffffu, v, o);
    __syncthreads();
    if (lane == 0) red[w] = v;
    __syncthreads();
    float s = (threadIdx.x < 8) ? red[threadIdx.x] : 0.f;
    if (w == 0) {
#pragma unroll
        for (int o = 4; o; o >>= 1) s += __shfl_down_sync(0xffffffffu, s, o);
        if (lane == 0) red[0] = s;
    }
    __syncthreads();
    return red[0];
}

// ---------------------------------------------------------------------------
// Finalize: one CTA per batch. exp/attn/geo + bilinear reduction + sigmoid.
// ---------------------------------------------------------------------------
__global__ __launch_bounds__(NT)
void finalize_kernel(const int* __restrict__ history, const int* __restrict__ target,
                     const float* __restrict__ hv, const float* __restrict__ dist,
                     float* __restrict__ out) {
    __shared__ float red[8];
    const int b = blockIdx.x, tid = threadIdx.x;
    const int tgt_i = target[b];

    float me = 0.f;
    if (tid < H) {
        float sc = g_swp[(size_t)(2 * b) * H + tid] +
                   g_swp[(size_t)(2 * b + 1) * H + tid];
        me = (history[b * H + tid] != tgt_i) ? __expf(sc) : 0.f;
    }
    float S = block_sum(me, red);

    float contrib = 0.f;
    if (tid < H) {
        float attn = me / sqrtf(S);                      // exp_sum ** 0.5
        float geo  = __expf(g_geo[tid] * dist[b * H + tid]);
        contrib = (attn + geo) * g_dv[(size_t)b * H + tid] +
                  hv[tid] * g_dt[(size_t)b * H + tid];
    }
    float pred = block_sum(contrib, red);
    if (tid == 0) out[b] = 1.0f / (1.0f + __expf(-pred));
}

// ---------------------------------------------------------------------------
extern "C" void kernel_launch(void* const* d_in, const int* in_sizes, int n_in,
                              void* d_out, int out_size) {
    const int*   history = (const int*)  d_in[0];
    const int*   target  = (const int*)  d_in[1];
    const int*   hregion = (const int*)  d_in[2];
    const int*   tregion = (const int*)  d_in[3];
    const float* hv      = (const float*)d_in[4];
    const float* dist    = (const float*)d_in[5];
    const int*   uid     = (const int*)  d_in[6];
    const float* embT    = (const float*)d_in[7];
    const float* embR    = (const float*)d_in[8];
    const float* embD    = (const float*)d_in[9];
    const float* Wq      = (const float*)d_in[10];
    const float* Wk      = (const float*)d_in[11];
    const float* Wv      = (const float*)d_in[12];
    float*       out     = (float*)d_out;

    int b          = in_sizes[1];          // 1024
    int region_num = in_sizes[8] / 64;     // 1000

    cudaFuncSetAttribute(mainA_kernel, cudaFuncAttributeMaxDynamicSharedMemorySize,
                         SMEM_A_BYTES);

    prep1_kernel<<<488, NT>>>(target, tregion, embT, embR, Wq, Wv, Wk,
                              hregion, embD, uid, b, region_num);
    gather_kernel<<<b, NT>>>(history, hregion, embT, embR);
    mainA_kernel<<<2 * b, NT, SMEM_A_BYTES>>>();
    finalize_kernel<<<b, NT>>>(history, target, hv, dist, out);
}